// round 1
// baseline (speedup 1.0000x reference)
#include <cuda_runtime.h>
#include <math.h>

#define MAX_NODES 101001
#define EMBED     64
#define MAX_EDGES 2020020
#define EPS_F     1e-12f

// Scratch (allocation-free: __device__ globals)
__device__ float g_ew[MAX_EDGES];        // logits, then exp(logit - rowmax)
__device__ float g_rs[MAX_NODES];        // 1 / max(rowsum, EPS)
__device__ int   g_rowptr[MAX_NODES + 1];

// ---------------------------------------------------------------------------
// K1: CSR row pointers via binary search over sorted edge_row
// ---------------------------------------------------------------------------
__global__ void k_rowptr(const int* __restrict__ erow, int n, int e) {
    int v = blockIdx.x * blockDim.x + threadIdx.x;
    if (v > n) return;
    int lo = 0, hi = e;
    while (lo < hi) {
        int mid = (lo + hi) >> 1;
        if (erow[mid] < v) lo = mid + 1; else hi = mid;
    }
    g_rowptr[v] = lo;
}

// ---------------------------------------------------------------------------
// K2: per-row edge softmax (warp per row).
// Pass 1: logits (coalesced 256B gather of t_att[col], warp dot-reduce), track max.
// Pass 2: exp + sum (lane-parallel over the segment), store exp, store 1/sum.
// ---------------------------------------------------------------------------
__global__ void k_softmax(const float* __restrict__ h_att,
                          const float* __restrict__ t_att,
                          const int*   __restrict__ ecol, int n) {
    int warp = (blockIdx.x * blockDim.x + threadIdx.x) >> 5;
    int lane = threadIdx.x & 31;
    if (warp >= n) return;
    int beg = g_rowptr[warp], end = g_rowptr[warp + 1];
    if (beg == end) return;

    float2 ha = ((const float2*)(h_att + (size_t)warp * EMBED))[lane];

    float m = -INFINITY;
    for (int e = beg; e < end; ++e) {
        int c = ecol[e];
        float2 ta = ((const float2*)(t_att + (size_t)c * EMBED))[lane];
        float p = ha.x * ta.x + ha.y * ta.y;
        #pragma unroll
        for (int o = 16; o; o >>= 1) p += __shfl_xor_sync(0xffffffffu, p, o);
        if (lane == 0) g_ew[e] = p;       // p identical across lanes post-reduce
        m = fmaxf(m, p);
    }
    __syncwarp();                          // make lane0's logit writes warp-visible

    float s = 0.f;
    for (int e = beg + lane; e < end; e += 32) {
        float ex = expf(g_ew[e] - m);
        g_ew[e] = ex;
        s += ex;
    }
    #pragma unroll
    for (int o = 16; o; o >>= 1) s += __shfl_xor_sync(0xffffffffu, s, o);
    if (lane == 0) g_rs[warp] = 1.f / fmaxf(s, EPS_F);
}

// ---------------------------------------------------------------------------
// K3: one propagation layer, fully fused (warp per row):
//   add = h_prev[row] + (1/s) * sum_e exp_e * h_prev[col_e]
//   h   = relu(add @ W^T + b);  out = h / max(||h||, EPS)
// W^T staged in shared as float2 so lane l reads Wt2[k*32+l] conflict-free.
// ---------------------------------------------------------------------------
__global__ void k_prop(const float* __restrict__ h_prev,
                       const int*   __restrict__ ecol,
                       const float* __restrict__ W,      // [64,64] row-major
                       const float* __restrict__ b,
                       float*       __restrict__ out, int n) {
    __shared__ float Wt[EMBED * EMBED];    // Wt[k*64+j] = W[j*64+k]
    __shared__ float bs[EMBED];
    __shared__ float2 addsh[8][EMBED / 2]; // 8 warps per block

    for (int i = threadIdx.x; i < EMBED * EMBED; i += blockDim.x) {
        int k = i >> 6, j = i & 63;
        Wt[i] = W[j * EMBED + k];
    }
    if (threadIdx.x < EMBED) bs[threadIdx.x] = b[threadIdx.x];
    __syncthreads();

    int wwarp = threadIdx.x >> 5;
    int lane  = threadIdx.x & 31;
    int row   = blockIdx.x * 8 + wwarp;
    if (row >= n) return;

    int beg = g_rowptr[row], end = g_rowptr[row + 1];

    float2 acc = make_float2(0.f, 0.f);
    for (int e = beg; e < end; ++e) {
        int c   = ecol[e];
        float w = g_ew[e];
        float2 hv = ((const float2*)(h_prev + (size_t)c * EMBED))[lane];
        acc.x = fmaf(w, hv.x, acc.x);
        acc.y = fmaf(w, hv.y, acc.y);
    }
    float rs  = (beg < end) ? g_rs[row] : 0.f;
    float2 hr = ((const float2*)(h_prev + (size_t)row * EMBED))[lane];
    acc.x = fmaf(rs, acc.x, hr.x);
    acc.y = fmaf(rs, acc.y, hr.y);

    addsh[wwarp][lane] = acc;
    __syncwarp();

    float2 o = make_float2(bs[2 * lane], bs[2 * lane + 1]);
    const float2* Wt2 = (const float2*)Wt;
    const float*  ash = (const float*)addsh[wwarp];
    #pragma unroll
    for (int k = 0; k < EMBED; ++k) {
        float  a  = ash[k];                // warp broadcast
        float2 wv = Wt2[k * 32 + lane];    // conflict-free
        o.x = fmaf(a, wv.x, o.x);
        o.y = fmaf(a, wv.y, o.y);
    }
    o.x = fmaxf(o.x, 0.f);
    o.y = fmaxf(o.y, 0.f);

    float sq = o.x * o.x + o.y * o.y;
    #pragma unroll
    for (int of = 16; of; of >>= 1) sq += __shfl_xor_sync(0xffffffffu, sq, of);
    float inv = 1.f / fmaxf(sqrtf(sq), EPS_F);

    ((float2*)(out + (size_t)row * EMBED))[lane] = make_float2(o.x * inv, o.y * inv);
}

// ---------------------------------------------------------------------------
extern "C" void kernel_launch(void* const* d_in, const int* in_sizes, int n_in,
                              void* d_out, int out_size) {
    const float* h0    = (const float*)d_in[0];
    const float* h_att = (const float*)d_in[1];
    const float* t_att = (const float*)d_in[2];
    const float* w1    = (const float*)d_in[3];
    const float* b1    = (const float*)d_in[4];
    const float* w2    = (const float*)d_in[5];
    const float* b2    = (const float*)d_in[6];
    const int*   erow  = (const int*)d_in[7];
    const int*   ecol  = (const int*)d_in[8];
    float* out = (float*)d_out;

    int n = in_sizes[0] / EMBED;
    int e = in_sizes[8];
    if (n > MAX_NODES) n = MAX_NODES;
    if (e > MAX_EDGES) e = MAX_EDGES;

    // layer 0 output = h0
    cudaMemcpyAsync(out, h0, (size_t)n * EMBED * sizeof(float),
                    cudaMemcpyDeviceToDevice, 0);

    {   // row pointers
        int threads = 256;
        int blocks  = (n + 1 + threads - 1) / threads;
        k_rowptr<<<blocks, threads>>>(erow, n, e);
    }
    {   // edge softmax
        int blocks = (n + 7) / 8;          // 8 warps (rows) per 256-thread block
        k_softmax<<<blocks, 256>>>(h_att, t_att, ecol, n);
    }
    {   // two propagation layers; layer 2 reads layer-1 slice of d_out
        int blocks = (n + 7) / 8;
        float* l1 = out + (size_t)n * EMBED;
        float* l2 = out + (size_t)2 * n * EMBED;
        k_prop<<<blocks, 256>>>(h0, ecol, w1, b1, l1, n);
        k_prop<<<blocks, 256>>>(l1, ecol, w2, b2, l2, n);
    }
}

// round 2
// speedup vs baseline: 1.0475x; 1.0475x over previous
#include <cuda_runtime.h>
#include <math.h>

#define MAX_NODES 101001
#define EMBED     64
#define MAX_EDGES 2020020
#define EPS_F     1e-12f
#define FULL      0xffffffffu

// Scratch (allocation-free: __device__ globals)
__device__ float g_ew[MAX_EDGES];        // logits, then exp(logit - rowmax)
__device__ float g_rs[MAX_NODES];        // 1 / max(rowsum, EPS)
__device__ int   g_rowptr[MAX_NODES + 1];

// ---------------------------------------------------------------------------
// K1: CSR row pointers via binary search over sorted edge_row
// ---------------------------------------------------------------------------
__global__ void k_rowptr(const int* __restrict__ erow, int n, int e) {
    int v = blockIdx.x * blockDim.x + threadIdx.x;
    if (v > n) return;
    int lo = 0, hi = e;
    while (lo < hi) {
        int mid = (lo + hi) >> 1;
        if (erow[mid] < v) lo = mid + 1; else hi = mid;
    }
    g_rowptr[v] = lo;
}

// ---------------------------------------------------------------------------
// K2: per-row edge softmax (warp per row), 2 edges per iteration.
// Lanes 0-15 handle edge j, lanes 16-31 edge j+1 (float4 = 16 lanes x 16B row).
// ecol batched coalesced (1 wavefront / 32 edges) then shfl-broadcast.
// ---------------------------------------------------------------------------
__global__ void k_softmax(const float* __restrict__ h_att,
                          const float* __restrict__ t_att,
                          const int*   __restrict__ ecol, int n) {
    int row  = (blockIdx.x * blockDim.x + threadIdx.x) >> 5;
    int lane = threadIdx.x & 31;
    if (row >= n) return;
    int beg = g_rowptr[row], end = g_rowptr[row + 1];
    if (beg == end) return;

    int half = lane >> 4;        // 0: edge j, 1: edge j+1
    int hl   = lane & 15;

    float4 ha = ((const float4*)(h_att + (size_t)row * EMBED))[hl];

    float m = -INFINITY;
    for (int base = beg; base < end; base += 32) {
        int idx = base + lane;
        int c   = (idx < end) ? ecol[idx] : 0;     // coalesced batch
        int cnt = min(32, end - base);
        for (int j = 0; j < cnt; j += 2) {
            int  jj = j + half; if (jj >= cnt) jj = cnt - 1;   // clamp odd tail
            int  cc = __shfl_sync(FULL, c, jj);
            float4 tv = ((const float4*)(t_att + (size_t)cc * EMBED))[hl];
            float p = ha.x * tv.x + ha.y * tv.y + ha.z * tv.z + ha.w * tv.w;
            #pragma unroll
            for (int o = 8; o; o >>= 1) p += __shfl_xor_sync(FULL, p, o);
            // p now uniform within each 16-lane half
            bool valid = (half == 0) || (j + 1 < cnt);
            if (valid) {
                if (hl == 0) g_ew[base + j + half] = p;
                m = fmaxf(m, p);
            }
        }
    }
    // warp-wide max
    #pragma unroll
    for (int o = 16; o; o >>= 1) m = fmaxf(m, __shfl_xor_sync(FULL, m, o));
    __syncwarp();

    float s = 0.f;
    for (int e = beg + lane; e < end; e += 32) {
        float ex = expf(g_ew[e] - m);
        g_ew[e] = ex;
        s += ex;
    }
    #pragma unroll
    for (int o = 16; o; o >>= 1) s += __shfl_xor_sync(FULL, s, o);
    if (lane == 0) g_rs[row] = 1.f / fmaxf(s, EPS_F);
}

// ---------------------------------------------------------------------------
// K3: one propagation layer, fully fused (warp per row), 2 edges/iteration:
//   add = h_prev[row] + (1/s) * sum_e exp_e * h_prev[col_e]
//   h   = relu(add @ W^T + b);  out = h / max(||h||, EPS)
// Gather: float4, lanes 0-15 = edge j, lanes 16-31 = edge j+1; halves summed
// at the end with shfl_xor(16). (ecol, ew) batched coalesced + broadcast.
// ---------------------------------------------------------------------------
__global__ void k_prop(const float* __restrict__ h_prev,
                       const int*   __restrict__ ecol,
                       const float* __restrict__ W,      // [64,64] row-major
                       const float* __restrict__ b,
                       float*       __restrict__ out, int n) {
    __shared__ float Wt[EMBED * EMBED];    // Wt[k*64+j] = W[j*64+k]
    __shared__ float bs[EMBED];
    __shared__ float addsh[8][EMBED];      // 8 warps per block

    for (int i = threadIdx.x; i < EMBED * EMBED; i += blockDim.x) {
        int k = i >> 6, j = i & 63;
        Wt[i] = W[j * EMBED + k];
    }
    if (threadIdx.x < EMBED) bs[threadIdx.x] = b[threadIdx.x];
    __syncthreads();

    int wwarp = threadIdx.x >> 5;
    int lane  = threadIdx.x & 31;
    int row   = blockIdx.x * 8 + wwarp;
    if (row >= n) return;

    int half = lane >> 4;
    int hl   = lane & 15;

    int beg = g_rowptr[row], end = g_rowptr[row + 1];

    float4 acc = make_float4(0.f, 0.f, 0.f, 0.f);
    for (int base = beg; base < end; base += 32) {
        int   idx = base + lane;
        bool  v   = idx < end;
        int   c   = v ? ecol[idx] : 0;     // coalesced batch: 1 wf / 32 edges
        float w   = v ? g_ew[idx] : 0.f;   // coalesced batch: 1 wf / 32 edges
        int   cnt = min(32, end - base);
        for (int j = 0; j < cnt; j += 2) {
            int   jj = j + half; if (jj >= cnt) jj = cnt - 1;
            int   cc = __shfl_sync(FULL, c, jj);
            float ww = __shfl_sync(FULL, w, jj);
            if (half && (j + 1 >= cnt)) ww = 0.f;   // kill duplicated tail edge
            float4 hv = ((const float4*)(h_prev + (size_t)cc * EMBED))[hl];
            acc.x = fmaf(ww, hv.x, acc.x);
            acc.y = fmaf(ww, hv.y, acc.y);
            acc.z = fmaf(ww, hv.z, acc.z);
            acc.w = fmaf(ww, hv.w, acc.w);
        }
    }
    // combine the two half-warp accumulators (same columns in both halves)
    acc.x += __shfl_xor_sync(FULL, acc.x, 16);
    acc.y += __shfl_xor_sync(FULL, acc.y, 16);
    acc.z += __shfl_xor_sync(FULL, acc.z, 16);
    acc.w += __shfl_xor_sync(FULL, acc.w, 16);

    float rs = (beg < end) ? g_rs[row] : 0.f;
    float4 hr = ((const float4*)(h_prev + (size_t)row * EMBED))[hl];
    acc.x = fmaf(rs, acc.x, hr.x);
    acc.y = fmaf(rs, acc.y, hr.y);
    acc.z = fmaf(rs, acc.z, hr.z);
    acc.w = fmaf(rs, acc.w, hr.w);

    if (half == 0) ((float4*)addsh[wwarp])[hl] = acc;
    __syncwarp();

    float2 o = make_float2(bs[2 * lane], bs[2 * lane + 1]);
    const float2* Wt2 = (const float2*)Wt;
    const float*  ash = addsh[wwarp];
    #pragma unroll
    for (int k = 0; k < EMBED; ++k) {
        float  a  = ash[k];                // broadcast, conflict-free
        float2 wv = Wt2[k * 32 + lane];    // conflict-free
        o.x = fmaf(a, wv.x, o.x);
        o.y = fmaf(a, wv.y, o.y);
    }
    o.x = fmaxf(o.x, 0.f);
    o.y = fmaxf(o.y, 0.f);

    float sq = o.x * o.x + o.y * o.y;
    #pragma unroll
    for (int of = 16; of; of >>= 1) sq += __shfl_xor_sync(FULL, sq, of);
    float inv = 1.f / fmaxf(sqrtf(sq), EPS_F);

    ((float2*)(out + (size_t)row * EMBED))[lane] = make_float2(o.x * inv, o.y * inv);
}

// ---------------------------------------------------------------------------
extern "C" void kernel_launch(void* const* d_in, const int* in_sizes, int n_in,
                              void* d_out, int out_size) {
    const float* h0    = (const float*)d_in[0];
    const float* h_att = (const float*)d_in[1];
    const float* t_att = (const float*)d_in[2];
    const float* w1    = (const float*)d_in[3];
    const float* b1    = (const float*)d_in[4];
    const float* w2    = (const float*)d_in[5];
    const float* b2    = (const float*)d_in[6];
    const int*   erow  = (const int*)d_in[7];
    const int*   ecol  = (const int*)d_in[8];
    float* out = (float*)d_out;

    int n = in_sizes[0] / EMBED;
    int e = in_sizes[8];
    if (n > MAX_NODES) n = MAX_NODES;
    if (e > MAX_EDGES) e = MAX_EDGES;

    // layer 0 output = h0
    cudaMemcpyAsync(out, h0, (size_t)n * EMBED * sizeof(float),
                    cudaMemcpyDeviceToDevice, 0);

    {   // row pointers
        int threads = 256;
        int blocks  = (n + 1 + threads - 1) / threads;
        k_rowptr<<<blocks, threads>>>(erow, n, e);
    }
    {   // edge softmax
        int blocks = (n + 7) / 8;          // 8 warps (rows) per 256-thread block
        k_softmax<<<blocks, 256>>>(h_att, t_att, ecol, n);
    }
    {   // two propagation layers; layer 2 reads layer-1 slice of d_out
        int blocks = (n + 7) / 8;
        float* l1 = out + (size_t)n * EMBED;
        float* l2 = out + (size_t)2 * n * EMBED;
        k_prop<<<blocks, 256>>>(h0, ecol, w1, b1, l1, n);
        k_prop<<<blocks, 256>>>(l1, ecol, w2, b2, l2, n);
    }
}